// round 9
// baseline (speedup 1.0000x reference)
#include <cuda_runtime.h>

typedef unsigned long long u64;

#define NK 16
#define TW 136           // tile row stride in floats (col c stores gcol = bx*128 + c - 4)

struct CB {
    u64 crec[NK][16];    // [u[i][j] i=0..3,j=0..2 (dup), mk(dup), pk(dup), pad, pad]
};

__device__   CB g_cb;
__constant__ CB c_cb;

__device__ __forceinline__ u64 pack2(float lo, float hi) {
    u64 r; asm("mov.b64 %0, {%1, %2};" : "=l"(r) : "f"(lo), "f"(hi)); return r;
}
__device__ __forceinline__ void unpack2(u64 v, float& lo, float& hi) {
    asm("mov.b64 {%0, %1}, %2;" : "=f"(lo), "=f"(hi) : "l"(v));
}
__device__ __forceinline__ u64 fma2(u64 a, u64 b, u64 c) {
    u64 d; asm("fma.rn.f32x2 %0, %1, %2, %3;" : "=l"(d) : "l"(a), "l"(b), "l"(c)); return d;
}
__device__ __forceinline__ u64 mul2_(u64 a, u64 b) {
    u64 d; asm("mul.rn.f32x2 %0, %1, %2;" : "=l"(d) : "l"(a), "l"(b)); return d;
}
__device__ __forceinline__ u64 add2_(u64 a, u64 b) {
    u64 d; asm("add.rn.f32x2 %0, %1, %2;" : "=l"(d) : "l"(a), "l"(b)); return d;
}
__device__ __forceinline__ u64 sub2_(u64 a, u64 b) {
    u64 d; asm("sub.rn.f32x2 %0, %1, %2;" : "=l"(d) : "l"(a), "l"(b)); return d;
}
// clamp (<=60, FMNMX on alu pipe) + ex2.approx on both halves, in place
__device__ __forceinline__ void ex2c_ip(u64& v) {
    asm("{\n\t"
        ".reg .f32 lo, hi;\n\t"
        "mov.b64 {lo, hi}, %0;\n\t"
        "min.f32 lo, lo, 0f42700000;\n\t"   // 60.0f
        "min.f32 hi, hi, 0f42700000;\n\t"
        "ex2.approx.f32 lo, lo;\n\t"
        "ex2.approx.f32 hi, hi;\n\t"
        "mov.b64 %0, {lo, hi};\n\t"
        "}" : "+l"(v));
}
// rcp.approx on both halves, in place
__device__ __forceinline__ u64 rcp2_(u64 v) {
    u64 d;
    asm("{\n\t"
        ".reg .f32 lo, hi;\n\t"
        "mov.b64 {lo, hi}, %1;\n\t"
        "rcp.approx.f32 lo, lo;\n\t"
        "rcp.approx.f32 hi, hi;\n\t"
        "mov.b64 %0, {lo, hi};\n\t"
        "}" : "=l"(d) : "l"(v));
    return d;
}
__device__ __forceinline__ float addsat_(float a, float b) {
    float r; asm("add.rn.sat.f32 %0, %1, %2;" : "=f"(r) : "f"(a), "f"(b)); return r;
}

#define C_SCALE (-14.4269504088896341f)   // -10*log2(e): conv emits w = -10*log2e*(N-r)

// Setup: Winograd F(2,3) weight transform in the w-domain + constants.
// g = C_SCALE * w_row;  u0=g0, u1=(g0+g1+g2)/2, u2=(g0-g1+g2)/2, u3=g2
__global__ void setup_kernel(const float* __restrict__ w,
                             const float* __restrict__ react,
                             const float* __restrict__ prod)
{
    int tid = threadIdx.x;            // 0..255 = NK*16
    int k = tid >> 4, j16 = tid & 15;
    u64 v = 0ull;
    if (j16 < 12) {
        int i = j16 / 3, jr = j16 - 3 * i;
        float g0 = C_SCALE * w[k * 9 + jr * 3 + 0];
        float g1 = C_SCALE * w[k * 9 + jr * 3 + 1];
        float g2 = C_SCALE * w[k * 9 + jr * 3 + 2];
        float u;
        if      (i == 0) u = g0;
        else if (i == 1) u = 0.5f * (g0 + g1 + g2);
        else if (i == 2) u = 0.5f * (g0 - g1 + g2);
        else             u = g2;
        v = pack2(u, u);
    } else if (j16 == 12) {
        float t = -C_SCALE * react[k];        // bias: w = C*N + (-C)*r
        v = pack2(t, t);
    } else if (j16 == 13) {
        float t = prod[k];                    // plain product
        v = pack2(t, t);
    }
    g_cb.crec[k][j16] = v;
}

// Grid: (4 col-tiles, 64 row-tiles, 16 batch). Block (64,4) = 256 thr.
// Thread: 2 rows x 2 cols = 4 px, packed as VERTICAL pairs (row0,row1) per column.
__global__ void __launch_bounds__(256, 4)
ca_kernel(const float* __restrict__ x, float* __restrict__ out)
{
    __shared__ __align__(16) float tile[10][TW];

    const int bx  = blockIdx.x;
    const int by  = blockIdx.y;
    const int b   = blockIdx.z;
    const int tx  = threadIdx.x;
    const int ty  = threadIdx.y;
    const int tid = ty * 64 + tx;

    // ---- tile load: 10 rows x 34 float4 ----
    const float* xb = x + (size_t)b * (512 * 512);
    #pragma unroll
    for (int it = 0; it < 2; it++) {
        int i = tid + it * 256;
        if (i < 340) {
            int r   = i / 34;
            int c4  = i - r * 34;
            int gy  = by * 8 + r - 1;
            int gc0 = bx * 128 + c4 * 4 - 4;
            float4 v = make_float4(0.f, 0.f, 0.f, 0.f);
            if ((unsigned)gy < 512u && (unsigned)gc0 < 512u)
                v = *(const float4*)(xb + (size_t)gy * 512 + gc0);
            *(float4*)&tile[r][c4 * 4] = v;
        }
    }
    __syncthreads();

    // ---- 4x4 input patch (rows q=0..3, cols gx-1..gx+2) ----
    float d0[4], d1[4], d2[4], d3[4];
    #pragma unroll
    for (int q = 0; q < 4; q++) {
        const float* trow = tile[2 * ty + q];
        d0[q] = trow[2 * tx + 3];
        u64 M = *(const u64*)(trow + 2 * tx + 4);
        unpack2(M, d1[q], d2[q]);
        d3[q] = trow[2 * tx + 6];
    }
    const u64 xc0 = pack2(d1[1], d1[2]);   // x centers col gx,   rows (0,1)
    const u64 xc1 = pack2(d2[1], d2[2]);   // x centers col gx+1, rows (0,1)

    // ---- input Winograd transform over vertical (q,q+1) pairs ----
    u64 P0[3], P1[3], P2[3], P3[3];
    #pragma unroll
    for (int j = 0; j < 3; j++) {
        u64 V0 = pack2(d0[j], d0[j + 1]);
        u64 V1 = pack2(d1[j], d1[j + 1]);
        u64 V2 = pack2(d2[j], d2[j + 1]);
        u64 V3 = pack2(d3[j], d3[j + 1]);
        P0[j] = sub2_(V0, V2);
        P1[j] = add2_(V1, V2);
        P2[j] = sub2_(V2, V1);
        P3[j] = sub2_(V1, V3);
    }

    const u64 ONE2 = pack2(1.0f, 1.0f);

    u64 aP0 = 0ull, aP1 = 0ull;   // sum(sigma_k * p_k), cols 0/1
    u64 aS0 = 0ull, aS1 = 0ull;   // sum(sigma_k)

    // ---- 8 k-pairs: conv both k's, ex2, merged single-rcp sigmoid pair ----
    #pragma unroll
    for (int j = 0; j < 8; j++) {
        const u64* crA = c_cb.crec[2 * j];
        const u64* crB = c_cb.crec[2 * j + 1];

        // conv kernel A -> wA (w-domain), bias folded into m1
        u64 m0 = mul2_(crA[0], P0[0]);
        u64 m1 = fma2(crA[3], P1[0], crA[12]);
        u64 m2 = mul2_(crA[6], P2[0]);
        u64 m3 = mul2_(crA[9], P3[0]);
        m0 = fma2(crA[1],  P0[1], m0);  m1 = fma2(crA[4],  P1[1], m1);
        m2 = fma2(crA[7],  P2[1], m2);  m3 = fma2(crA[10], P3[1], m3);
        m0 = fma2(crA[2],  P0[2], m0);  m1 = fma2(crA[5],  P1[2], m1);
        m2 = fma2(crA[8],  P2[2], m2);  m3 = fma2(crA[11], P3[2], m3);
        u64 sA  = add2_(m1, m2);
        u64 dA  = sub2_(m1, m2);
        u64 tA0 = add2_(m0, sA);     // col gx
        u64 tA1 = sub2_(dA, m3);     // col gx+1
        ex2c_ip(tA0);                // t = 2^w  (clamped w<=60)
        ex2c_ip(tA1);

        // conv kernel B -> wB
        m0 = mul2_(crB[0], P0[0]);
        m1 = fma2(crB[3], P1[0], crB[12]);
        m2 = mul2_(crB[6], P2[0]);
        m3 = mul2_(crB[9], P3[0]);
        m0 = fma2(crB[1],  P0[1], m0);  m1 = fma2(crB[4],  P1[1], m1);
        m2 = fma2(crB[7],  P2[1], m2);  m3 = fma2(crB[10], P3[1], m3);
        m0 = fma2(crB[2],  P0[2], m0);  m1 = fma2(crB[5],  P1[2], m1);
        m2 = fma2(crB[8],  P2[2], m2);  m3 = fma2(crB[11], P3[2], m3);
        u64 sB  = add2_(m1, m2);
        u64 dB  = sub2_(m1, m2);
        u64 tB0 = add2_(m0, sB);
        u64 tB1 = sub2_(dB, m3);
        ex2c_ip(tB0);
        ex2c_ip(tB1);

        const u64 pA = crA[13], pB = crB[13];

        // merged sigmoid pair, col gx: one rcp serves sigma_A + sigma_B
        {
            u64 u1 = add2_(tA0, ONE2);
            u64 u2 = add2_(tB0, ONE2);
            u64 r  = rcp2_(mul2_(u1, u2));
            u64 nS = add2_(u1, u2);                 // sigmaA+sigmaB numerator
            u64 nP = fma2(u2, pA, mul2_(u1, pB));   // pA*u2 + pB*u1
            aS0 = fma2(nS, r, aS0);
            aP0 = fma2(nP, r, aP0);
        }
        // col gx+1
        {
            u64 u1 = add2_(tA1, ONE2);
            u64 u2 = add2_(tB1, ONE2);
            u64 r  = rcp2_(mul2_(u1, u2));
            u64 nS = add2_(u1, u2);
            u64 nP = fma2(u2, pA, mul2_(u1, pB));
            aS1 = fma2(nS, r, aS1);
            aP1 = fma2(nP, r, aP1);
        }
    }

    // ---- epilogue: out = sat( x*(1 - aS) + aP ) ----
    u64 o0 = fma2(xc0, sub2_(ONE2, aS0), aP0);
    u64 o1 = fma2(xc1, sub2_(ONE2, aS1), aP1);
    float a0, a1, b0, b1;
    unpack2(o0, a0, a1);    // a0 = row0 col0, a1 = row1 col0
    unpack2(o1, b0, b1);

    const int gy0 = by * 8 + 2 * ty;
    float* ob = out + (size_t)b * (512 * 512) + (size_t)gy0 * 512 + bx * 128 + 2 * tx;
    *(float2*)ob         = make_float2(addsat_(a0, 0.0f), addsat_(b0, 0.0f));
    *(float2*)(ob + 512) = make_float2(addsat_(a1, 0.0f), addsat_(b1, 0.0f));
}

extern "C" void kernel_launch(void* const* d_in, const int* in_sizes, int n_in,
                              void* d_out, int out_size) {
    const float* x = (const float*)d_in[0];
    const float* w = (const float*)d_in[1];
    const float* r = (const float*)d_in[2];
    const float* p = (const float*)d_in[3];

    setup_kernel<<<1, 256>>>(w, r, p);

    void* gsym = nullptr;
    cudaGetSymbolAddress(&gsym, g_cb);
    cudaMemcpyToSymbolAsync(c_cb, gsym, sizeof(CB), 0, cudaMemcpyDeviceToDevice, 0);

    dim3 grid(4, 64, 16);
    dim3 block(64, 4);
    ca_kernel<<<grid, block>>>(x, (float*)d_out);
}